// round 13
// baseline (speedup 1.0000x reference)
#include <cuda_runtime.h>
#include <cuda_bf16.h>
#include <cuda_fp16.h>
#include <mma.h>
#include <math_constants.h>

using namespace nvcuda;

// Problem constants
#define N_NODES   50000
#define N_EDGES   800000
#define IN_FEATS  256
#define EDGE_FEATS 64
#define NUM_HEADS 4
#define OUT_FEATS 32
#define HF        128           // NUM_HEADS*OUT_FEATS
#define QCOLS     256           // NUM_HEADS*EDGE_FEATS
#define NCAT      384           // HF + QCOLS

#define SCAN_BLK  512
#define NB_SCAN   ((N_NODES + SCAN_BLK - 1) / SCAN_BLK)   // 98

#define GM_BM 128
#define GM_BK 32

// Scratch (static device globals; no allocation allowed)
__device__ __half g_wcat[IN_FEATS * NCAT];     // [W_node | W_node@Wbig*scale] fp16
__device__ __half g_hh[N_NODES * HF];          // projected node feats fp16
__device__ __half g_qh[N_NODES * QCOLS];       // q[n,h,k] fp16 (scale baked in)
__device__ float  g_w[N_EDGES * NUM_HEADS];    // exp(score), CSR order
__device__ int    g_cnt[N_NODES];
__device__ int    g_off[N_NODES + 1];
__device__ int    g_cur[N_NODES];
__device__ int2   g_es[N_EDGES];               // (eid, src) grouped by dst
__device__ int    g_part[NB_SCAN];
__device__ int    g_partx[NB_SCAN];

// ---------------------------------------------------------------------------
__global__ void zero_cnt_kernel() {
    int i = blockIdx.x * blockDim.x + threadIdx.x;
    if (i < N_NODES) g_cnt[i] = 0;
}

// ---------------------------------------------------------------------------
// Wcat precompute.
// ---------------------------------------------------------------------------
__global__ __launch_bounds__(NCAT) void wcat_kernel(
    const float* __restrict__ Wn, const float* __restrict__ We) {
    __shared__ float We_s[EDGE_FEATS * HF];   // 32KB
    __shared__ float wn_row[HF];

    const int c_in = blockIdx.x;
    const int j = threadIdx.x;

    for (int i = j; i < EDGE_FEATS * HF; i += NCAT) We_s[i] = We[i];
    if (j < HF) wn_row[j] = Wn[(size_t)c_in * HF + j];
    __syncthreads();

    float out;
    if (j < HF) {
        out = wn_row[j];
    } else {
        const int jj = j - HF;
        const int h = jj >> 6;
        const int k = jj & 63;
        float acc = 0.0f;
#pragma unroll
        for (int f = 0; f < OUT_FEATS; f++)
            acc += wn_row[h * OUT_FEATS + f] * We_s[k * HF + h * OUT_FEATS + f];
        out = acc * 0.17677669529663687f;   // 1/sqrt(32)
    }
    g_wcat[(size_t)c_in * NCAT + j] = __float2half_rn(out);
}

// ---------------------------------------------------------------------------
// Single fused GEMM: [h | q] = A[50000,256] @ Wcat[256,384], wmma fp16/fp32.
// ---------------------------------------------------------------------------
__global__ __launch_bounds__(256) void gemm_cat_kernel(const float* __restrict__ A) {
    __shared__ __half As[2][GM_BM][GM_BK + 8];
    __shared__ __half Ws[2][GM_BK][128 + 8];
    __shared__ float  patch[8][16 * 16];

    const int tid  = threadIdx.x;
    const int warp = tid >> 5;
    const int lane = tid & 31;
    const int wm   = warp >> 1;
    const int wn   = warp & 1;
    const int m0   = blockIdx.y * GM_BM;
    const int nbase = blockIdx.x * 128;

    const int ar = tid >> 3;
    const int ac = (tid & 7) * 4;
    const int wr = tid >> 4;
    const int wc = (tid & 15) * 8;

    wmma::fragment<wmma::accumulator, 16, 16, 16, float> c[2][4];
#pragma unroll
    for (int i = 0; i < 2; i++)
#pragma unroll
        for (int j = 0; j < 4; j++) wmma::fill_fragment(c[i][j], 0.0f);

    float4 areg[4];
    uint4  wreg[2];

#pragma unroll
    for (int i = 0; i < 4; i++) {
        int gr = m0 + ar + i * 32;
        areg[i] = make_float4(0.f, 0.f, 0.f, 0.f);
        if (gr < N_NODES) areg[i] = *(const float4*)&A[(size_t)gr * IN_FEATS + ac];
    }
#pragma unroll
    for (int i = 0; i < 2; i++)
        wreg[i] = *(const uint4*)&g_wcat[(size_t)(wr + i * 16) * NCAT + nbase + wc];

#pragma unroll
    for (int i = 0; i < 4; i++) {
        As[0][ar + i * 32][ac + 0] = __float2half_rn(areg[i].x);
        As[0][ar + i * 32][ac + 1] = __float2half_rn(areg[i].y);
        As[0][ar + i * 32][ac + 2] = __float2half_rn(areg[i].z);
        As[0][ar + i * 32][ac + 3] = __float2half_rn(areg[i].w);
    }
#pragma unroll
    for (int i = 0; i < 2; i++)
        *(uint4*)&Ws[0][wr + i * 16][wc] = wreg[i];
    __syncthreads();

    int buf = 0;
#pragma unroll
    for (int k0 = 0; k0 < IN_FEATS; k0 += GM_BK) {
        const bool has_next = (k0 + GM_BK < IN_FEATS);

        if (has_next) {
            const int kn = k0 + GM_BK;
#pragma unroll
            for (int i = 0; i < 4; i++) {
                int gr = m0 + ar + i * 32;
                areg[i] = make_float4(0.f, 0.f, 0.f, 0.f);
                if (gr < N_NODES) areg[i] = *(const float4*)&A[(size_t)gr * IN_FEATS + kn + ac];
            }
#pragma unroll
            for (int i = 0; i < 2; i++)
                wreg[i] = *(const uint4*)&g_wcat[(size_t)(kn + wr + i * 16) * NCAT + nbase + wc];
        }

#pragma unroll
        for (int kk = 0; kk < GM_BK; kk += 16) {
            wmma::fragment<wmma::matrix_a, 16, 16, 16, __half, wmma::row_major> a[2];
            wmma::fragment<wmma::matrix_b, 16, 16, 16, __half, wmma::row_major> b[4];
#pragma unroll
            for (int i = 0; i < 2; i++)
                wmma::load_matrix_sync(a[i], &As[buf][wm * 32 + i * 16][kk], GM_BK + 8);
#pragma unroll
            for (int j = 0; j < 4; j++)
                wmma::load_matrix_sync(b[j], &Ws[buf][kk][wn * 64 + j * 16], 128 + 8);
#pragma unroll
            for (int i = 0; i < 2; i++)
#pragma unroll
                for (int j = 0; j < 4; j++)
                    wmma::mma_sync(c[i][j], a[i], b[j], c[i][j]);
        }

        if (has_next) {
            const int nb = buf ^ 1;
#pragma unroll
            for (int i = 0; i < 4; i++) {
                As[nb][ar + i * 32][ac + 0] = __float2half_rn(areg[i].x);
                As[nb][ar + i * 32][ac + 1] = __float2half_rn(areg[i].y);
                As[nb][ar + i * 32][ac + 2] = __float2half_rn(areg[i].z);
                As[nb][ar + i * 32][ac + 3] = __float2half_rn(areg[i].w);
            }
#pragma unroll
            for (int i = 0; i < 2; i++)
                *(uint4*)&Ws[nb][wr + i * 16][wc] = wreg[i];
            __syncthreads();
            buf = nb;
        }
    }

    __syncthreads();
    const int prow = lane >> 1;
    const int pcol = (lane & 1) * 8;
#pragma unroll
    for (int i = 0; i < 2; i++) {
#pragma unroll
        for (int j = 0; j < 4; j++) {
            wmma::store_matrix_sync(patch[warp], c[i][j], 16, wmma::mem_row_major);
            __syncwarp();
            const int n = m0 + wm * 32 + i * 16 + prow;
            if (n < N_NODES) {
                const float* pr = patch[warp] + prow * 16 + pcol;
                union { uint4 u; __half2 h2[4]; } pack;
                pack.h2[0] = __floats2half2_rn(pr[0], pr[1]);
                pack.h2[1] = __floats2half2_rn(pr[2], pr[3]);
                pack.h2[2] = __floats2half2_rn(pr[4], pr[5]);
                pack.h2[3] = __floats2half2_rn(pr[6], pr[7]);
                const int C = nbase + wn * 64 + j * 16 + pcol;
                if (C < HF) {
                    *(uint4*)&g_hh[(size_t)n * HF + C] = pack.u;
                } else {
                    *(uint4*)&g_qh[(size_t)n * QCOLS + (C - HF)] = pack.u;
                }
            }
            __syncwarp();
        }
    }
}

// ---------------------------------------------------------------------------
// CSR build: histogram -> scan (3 kernels) -> scatter (packed int2)
// ---------------------------------------------------------------------------
__global__ void hist_kernel(const int* __restrict__ dst) {
    int e = blockIdx.x * blockDim.x + threadIdx.x;
    if (e < N_EDGES) atomicAdd(&g_cnt[dst[e]], 1);
}

__global__ __launch_bounds__(SCAN_BLK) void scan1_kernel() {
    __shared__ int sm[SCAN_BLK];
    int t = threadIdx.x;
    int i = blockIdx.x * SCAN_BLK + t;
    sm[t] = (i < N_NODES) ? g_cnt[i] : 0;
    __syncthreads();
    for (int off = SCAN_BLK / 2; off > 0; off >>= 1) {
        if (t < off) sm[t] += sm[t + off];
        __syncthreads();
    }
    if (t == 0) g_part[blockIdx.x] = sm[0];
}

__global__ __launch_bounds__(128) void scan2_kernel() {
    __shared__ int sm[2][128];
    int t = threadIdx.x;
    int v = (t < NB_SCAN) ? g_part[t] : 0;
    int pi = 0;
    sm[0][t] = v;
    __syncthreads();
#pragma unroll
    for (int off = 1; off < 128; off <<= 1) {
        int add = (t >= off) ? sm[pi][t - off] : 0;
        sm[pi ^ 1][t] = sm[pi][t] + add;
        pi ^= 1;
        __syncthreads();
    }
    if (t < NB_SCAN) g_partx[t] = sm[pi][t] - v;   // exclusive
}

__global__ __launch_bounds__(SCAN_BLK) void scan3_kernel() {
    __shared__ int sm[2][SCAN_BLK];
    int t = threadIdx.x;
    int i = blockIdx.x * SCAN_BLK + t;
    int v = (i < N_NODES) ? g_cnt[i] : 0;
    int pi = 0;
    sm[0][t] = v;
    __syncthreads();
#pragma unroll
    for (int off = 1; off < SCAN_BLK; off <<= 1) {
        int add = (t >= off) ? sm[pi][t - off] : 0;
        sm[pi ^ 1][t] = sm[pi][t] + add;
        pi ^= 1;
        __syncthreads();
    }
    if (i < N_NODES) {
        int excl = g_partx[blockIdx.x] + sm[pi][t] - v;
        g_off[i] = excl;
        g_cur[i] = excl;
    }
    if (blockIdx.x == 0 && t == 0) g_off[N_NODES] = N_EDGES;
}

__global__ void scatter_kernel(const int* __restrict__ src, const int* __restrict__ dst) {
    int e = blockIdx.x * blockDim.x + threadIdx.x;
    if (e < N_EDGES) {
        int pos = atomicAdd(&g_cur[dst[e]], 1);
        g_es[pos] = make_int2(e, src[e]);
    }
}

// ---------------------------------------------------------------------------
// score: warp per CSR slot j — LOOP-FREE, fully edge-parallel.
// lane l: head h=l>>3, k-chunk k0=(l&7)*8.
// w[j*4+h] = exp(leaky(ef[eid] . q[src,h]))   (no max; softmax shift-invar.)
// ---------------------------------------------------------------------------
__global__ __launch_bounds__(256) void score_kernel(const float* __restrict__ ef) {
    const int j = (blockIdx.x * 256 + threadIdx.x) >> 5;
    if (j >= N_EDGES) return;
    const int lane = threadIdx.x & 31;
    const int h  = lane >> 3;
    const int k0 = (lane & 7) * 8;

    const int2 es = __ldg(&g_es[j]);
    const int eid = es.x;
    const int s   = es.y;

    const float4 ef0 = *(const float4*)(ef + (size_t)eid * EDGE_FEATS + k0);
    const float4 ef1 = *(const float4*)(ef + (size_t)eid * EDGE_FEATS + k0 + 4);

    const uint4 qv = *(const uint4*)(g_qh + (size_t)s * QCOLS + h * EDGE_FEATS + k0);
    const float2 q0 = __half22float2(*(const __half2*)&qv.x);
    const float2 q1 = __half22float2(*(((const __half2*)&qv.x) + 1));
    const float2 q2 = __half22float2(*(const __half2*)&qv.z);
    const float2 q3 = __half22float2(*(((const __half2*)&qv.z) + 1));

    float p = ef0.x * q0.x + ef0.y * q0.y + ef0.z * q1.x + ef0.w * q1.y
            + ef1.x * q2.x + ef1.y * q2.y + ef1.z * q3.x + ef1.w * q3.y;
    p += __shfl_xor_sync(0xffffffffu, p, 1);
    p += __shfl_xor_sync(0xffffffffu, p, 2);
    p += __shfl_xor_sync(0xffffffffu, p, 4);

    const float sc = (p > 0.0f) ? p : 0.01f * p;   // leaky relu
    if ((lane & 7) == 0)
        g_w[(size_t)j * NUM_HEADS + h] = __expf(sc);
}

// ---------------------------------------------------------------------------
// agg: warp per dst node. Light loop: per edge only w (16B bcast), src (8B),
// hh gather (256B). No shuffles, no exp — pure FMA accumulation.
// ---------------------------------------------------------------------------
__global__ __launch_bounds__(256) void agg_kernel(float* __restrict__ out) {
    const int d = (blockIdx.x * 256 + threadIdx.x) >> 5;
    if (d >= N_NODES) return;
    const int lane = threadIdx.x & 31;
    const int h = lane >> 3;

    const int beg = __ldg(&g_off[d]);
    const int end = __ldg(&g_off[d + 1]);

    float den = 0.0f;
    float4 acc = make_float4(0.f, 0.f, 0.f, 0.f);

    if (beg < end) {
        const int last = end - 1;
        int s0 = __ldg(&g_es[beg].y);
        float w0 = __ldg(&g_w[(size_t)beg * NUM_HEADS + h]);
        int s1; float w1;
        if (beg < last) {
            s1 = __ldg(&g_es[beg + 1].y);
            w1 = __ldg(&g_w[(size_t)(beg + 1) * NUM_HEADS + h]);
        } else { s1 = s0; w1 = w0; }

#pragma unroll 2
        for (int j = beg; j < end; j++) {
            const int s_c   = s0;
            const float w_c = w0;
            s0 = s1; w0 = w1;
            const int jn2 = (j + 2 < end) ? j + 2 : last;
            s1 = __ldg(&g_es[jn2].y);
            w1 = __ldg(&g_w[(size_t)jn2 * NUM_HEADS + h]);

            const uint2 hvu = *(const uint2*)(g_hh + (size_t)s_c * HF + lane * 4);
            const float2 h01 = __half22float2(*(const __half2*)&hvu.x);
            const float2 h23 = __half22float2(*(const __half2*)&hvu.y);

            den   += w_c;
            acc.x += w_c * h01.x;
            acc.y += w_c * h01.y;
            acc.z += w_c * h23.x;
            acc.w += w_c * h23.y;
        }
    }

    const float inv = (den > 0.0f) ? __frcp_rn(den) : 0.0f;
    float4 o = make_float4(acc.x * inv, acc.y * inv, acc.z * inv, acc.w * inv);
    *(float4*)(out + (size_t)d * HF + lane * 4) = o;
}

// ---------------------------------------------------------------------------
// True fork/join (no legacy-stream launches inside the forked region).
// ---------------------------------------------------------------------------
extern "C" void kernel_launch(void* const* d_in, const int* in_sizes, int n_in,
                              void* d_out, int out_size) {
    const float* node_feat = (const float*)d_in[0];
    const float* edge_feat = (const float*)d_in[1];
    const int*   src       = (const int*)d_in[2];
    const int*   dst       = (const int*)d_in[3];
    const float* W_node    = (const float*)d_in[4];
    const float* W_edge    = (const float*)d_in[5];
    float* out = (float*)d_out;

    static cudaStream_t sA = nullptr, sB = nullptr;
    static cudaEvent_t evFork = nullptr, evA = nullptr, evB = nullptr;
    if (sA == nullptr) {
        cudaStreamCreateWithFlags(&sA, cudaStreamNonBlocking);
        cudaStreamCreateWithFlags(&sB, cudaStreamNonBlocking);
        cudaEventCreateWithFlags(&evFork, cudaEventDisableTiming);
        cudaEventCreateWithFlags(&evA, cudaEventDisableTiming);
        cudaEventCreateWithFlags(&evB, cudaEventDisableTiming);
    }

    // fork from the capture-origin (default) stream
    cudaEventRecord(evFork, 0);
    cudaStreamWaitEvent(sA, evFork, 0);
    cudaStreamWaitEvent(sB, evFork, 0);

    // branch A: projection GEMM chain on sA
    wcat_kernel<<<IN_FEATS, NCAT, 0, sA>>>(W_node, W_edge);
    {
        dim3 ggrid(3, (N_NODES + GM_BM - 1) / GM_BM);
        gemm_cat_kernel<<<ggrid, 256, 0, sA>>>(node_feat);
    }
    cudaEventRecord(evA, sA);

    // branch B: CSR build on sB
    zero_cnt_kernel<<<(N_NODES + 255) / 256, 256, 0, sB>>>();
    hist_kernel<<<(N_EDGES + 255) / 256, 256, 0, sB>>>(dst);
    scan1_kernel<<<NB_SCAN, SCAN_BLK, 0, sB>>>();
    scan2_kernel<<<1, 128, 0, sB>>>();
    scan3_kernel<<<NB_SCAN, SCAN_BLK, 0, sB>>>();
    scatter_kernel<<<(N_EDGES + 255) / 256, 256, 0, sB>>>(src, dst);
    cudaEventRecord(evB, sB);

    // join on default stream, then consume both branches
    cudaStreamWaitEvent(0, evA, 0);
    cudaStreamWaitEvent(0, evB, 0);
    score_kernel<<<(N_EDGES * 32 + 255) / 256, 256>>>(edge_feat);
    agg_kernel<<<(N_NODES * 32 + 255) / 256, 256>>>(out);
}

// round 14
// speedup vs baseline: 1.1372x; 1.1372x over previous
#include <cuda_runtime.h>
#include <cuda_bf16.h>
#include <cuda_fp16.h>
#include <mma.h>
#include <math_constants.h>

using namespace nvcuda;

// Problem constants
#define N_NODES   50000
#define N_EDGES   800000
#define IN_FEATS  256
#define EDGE_FEATS 64
#define NUM_HEADS 4
#define OUT_FEATS 32
#define HF        128           // NUM_HEADS*OUT_FEATS
#define QCOLS     256           // NUM_HEADS*EDGE_FEATS
#define NCAT      384           // HF + QCOLS

#define SCAN_BLK  512
#define NB_SCAN   ((N_NODES + SCAN_BLK - 1) / SCAN_BLK)   // 98

#define GM_BM 128
#define GM_BK 32

// Scratch (static device globals; no allocation allowed)
__device__ __half g_wcat[IN_FEATS * NCAT];     // [W_node | W_node@Wbig*scale] fp16
__device__ __half g_hh[N_NODES * HF];          // projected node feats fp16
__device__ __half g_qh[N_NODES * QCOLS];       // q[n,h,k] fp16 (scale baked in)
__device__ int    g_cnt[N_NODES];
__device__ int    g_off[N_NODES + 1];
__device__ int    g_cur[N_NODES];
__device__ int2   g_es[N_EDGES];               // (eid, src) grouped by dst
__device__ int    g_part[NB_SCAN];
__device__ int    g_partx[NB_SCAN];

// ---------------------------------------------------------------------------
__global__ void zero_cnt_kernel() {
    int i = blockIdx.x * blockDim.x + threadIdx.x;
    if (i < N_NODES) g_cnt[i] = 0;
}

// ---------------------------------------------------------------------------
// Wcat precompute.
// ---------------------------------------------------------------------------
__global__ __launch_bounds__(NCAT) void wcat_kernel(
    const float* __restrict__ Wn, const float* __restrict__ We) {
    __shared__ float We_s[EDGE_FEATS * HF];   // 32KB
    __shared__ float wn_row[HF];

    const int c_in = blockIdx.x;
    const int j = threadIdx.x;

    for (int i = j; i < EDGE_FEATS * HF; i += NCAT) We_s[i] = We[i];
    if (j < HF) wn_row[j] = Wn[(size_t)c_in * HF + j];
    __syncthreads();

    float out;
    if (j < HF) {
        out = wn_row[j];
    } else {
        const int jj = j - HF;
        const int h = jj >> 6;
        const int k = jj & 63;
        float acc = 0.0f;
#pragma unroll
        for (int f = 0; f < OUT_FEATS; f++)
            acc += wn_row[h * OUT_FEATS + f] * We_s[k * HF + h * OUT_FEATS + f];
        out = acc * 0.17677669529663687f;   // 1/sqrt(32)
    }
    g_wcat[(size_t)c_in * NCAT + j] = __float2half_rn(out);
}

// ---------------------------------------------------------------------------
// Single fused GEMM: [h | q] = A[50000,256] @ Wcat[256,384], wmma fp16/fp32.
// ---------------------------------------------------------------------------
__global__ __launch_bounds__(256) void gemm_cat_kernel(const float* __restrict__ A) {
    __shared__ __half As[2][GM_BM][GM_BK + 8];
    __shared__ __half Ws[2][GM_BK][128 + 8];
    __shared__ float  patch[8][16 * 16];

    const int tid  = threadIdx.x;
    const int warp = tid >> 5;
    const int lane = tid & 31;
    const int wm   = warp >> 1;
    const int wn   = warp & 1;
    const int m0   = blockIdx.y * GM_BM;
    const int nbase = blockIdx.x * 128;

    const int ar = tid >> 3;
    const int ac = (tid & 7) * 4;
    const int wr = tid >> 4;
    const int wc = (tid & 15) * 8;

    wmma::fragment<wmma::accumulator, 16, 16, 16, float> c[2][4];
#pragma unroll
    for (int i = 0; i < 2; i++)
#pragma unroll
        for (int j = 0; j < 4; j++) wmma::fill_fragment(c[i][j], 0.0f);

    float4 areg[4];
    uint4  wreg[2];

#pragma unroll
    for (int i = 0; i < 4; i++) {
        int gr = m0 + ar + i * 32;
        areg[i] = make_float4(0.f, 0.f, 0.f, 0.f);
        if (gr < N_NODES) areg[i] = *(const float4*)&A[(size_t)gr * IN_FEATS + ac];
    }
#pragma unroll
    for (int i = 0; i < 2; i++)
        wreg[i] = *(const uint4*)&g_wcat[(size_t)(wr + i * 16) * NCAT + nbase + wc];

#pragma unroll
    for (int i = 0; i < 4; i++) {
        As[0][ar + i * 32][ac + 0] = __float2half_rn(areg[i].x);
        As[0][ar + i * 32][ac + 1] = __float2half_rn(areg[i].y);
        As[0][ar + i * 32][ac + 2] = __float2half_rn(areg[i].z);
        As[0][ar + i * 32][ac + 3] = __float2half_rn(areg[i].w);
    }
#pragma unroll
    for (int i = 0; i < 2; i++)
        *(uint4*)&Ws[0][wr + i * 16][wc] = wreg[i];
    __syncthreads();

    int buf = 0;
#pragma unroll
    for (int k0 = 0; k0 < IN_FEATS; k0 += GM_BK) {
        const bool has_next = (k0 + GM_BK < IN_FEATS);

        if (has_next) {
            const int kn = k0 + GM_BK;
#pragma unroll
            for (int i = 0; i < 4; i++) {
                int gr = m0 + ar + i * 32;
                areg[i] = make_float4(0.f, 0.f, 0.f, 0.f);
                if (gr < N_NODES) areg[i] = *(const float4*)&A[(size_t)gr * IN_FEATS + kn + ac];
            }
#pragma unroll
            for (int i = 0; i < 2; i++)
                wreg[i] = *(const uint4*)&g_wcat[(size_t)(kn + wr + i * 16) * NCAT + nbase + wc];
        }

#pragma unroll
        for (int kk = 0; kk < GM_BK; kk += 16) {
            wmma::fragment<wmma::matrix_a, 16, 16, 16, __half, wmma::row_major> a[2];
            wmma::fragment<wmma::matrix_b, 16, 16, 16, __half, wmma::row_major> b[4];
#pragma unroll
            for (int i = 0; i < 2; i++)
                wmma::load_matrix_sync(a[i], &As[buf][wm * 32 + i * 16][kk], GM_BK + 8);
#pragma unroll
            for (int j = 0; j < 4; j++)
                wmma::load_matrix_sync(b[j], &Ws[buf][kk][wn * 64 + j * 16], 128 + 8);
#pragma unroll
            for (int i = 0; i < 2; i++)
#pragma unroll
                for (int j = 0; j < 4; j++)
                    wmma::mma_sync(c[i][j], a[i], b[j], c[i][j]);
        }

        if (has_next) {
            const int nb = buf ^ 1;
#pragma unroll
            for (int i = 0; i < 4; i++) {
                As[nb][ar + i * 32][ac + 0] = __float2half_rn(areg[i].x);
                As[nb][ar + i * 32][ac + 1] = __float2half_rn(areg[i].y);
                As[nb][ar + i * 32][ac + 2] = __float2half_rn(areg[i].z);
                As[nb][ar + i * 32][ac + 3] = __float2half_rn(areg[i].w);
            }
#pragma unroll
            for (int i = 0; i < 2; i++)
                *(uint4*)&Ws[nb][wr + i * 16][wc] = wreg[i];
            __syncthreads();
            buf = nb;
        }
    }

    __syncthreads();
    const int prow = lane >> 1;
    const int pcol = (lane & 1) * 8;
#pragma unroll
    for (int i = 0; i < 2; i++) {
#pragma unroll
        for (int j = 0; j < 4; j++) {
            wmma::store_matrix_sync(patch[warp], c[i][j], 16, wmma::mem_row_major);
            __syncwarp();
            const int n = m0 + wm * 32 + i * 16 + prow;
            if (n < N_NODES) {
                const float* pr = patch[warp] + prow * 16 + pcol;
                union { uint4 u; __half2 h2[4]; } pack;
                pack.h2[0] = __floats2half2_rn(pr[0], pr[1]);
                pack.h2[1] = __floats2half2_rn(pr[2], pr[3]);
                pack.h2[2] = __floats2half2_rn(pr[4], pr[5]);
                pack.h2[3] = __floats2half2_rn(pr[6], pr[7]);
                const int C = nbase + wn * 64 + j * 16 + pcol;
                if (C < HF) {
                    *(uint4*)&g_hh[(size_t)n * HF + C] = pack.u;
                } else {
                    *(uint4*)&g_qh[(size_t)n * QCOLS + (C - HF)] = pack.u;
                }
            }
            __syncwarp();
        }
    }
}

// ---------------------------------------------------------------------------
// CSR build: histogram -> scan (3 kernels) -> scatter (packed int2)
// ---------------------------------------------------------------------------
__global__ void hist_kernel(const int* __restrict__ dst) {
    int e = blockIdx.x * blockDim.x + threadIdx.x;
    if (e < N_EDGES) atomicAdd(&g_cnt[dst[e]], 1);
}

__global__ __launch_bounds__(SCAN_BLK) void scan1_kernel() {
    __shared__ int sm[SCAN_BLK];
    int t = threadIdx.x;
    int i = blockIdx.x * SCAN_BLK + t;
    sm[t] = (i < N_NODES) ? g_cnt[i] : 0;
    __syncthreads();
    for (int off = SCAN_BLK / 2; off > 0; off >>= 1) {
        if (t < off) sm[t] += sm[t + off];
        __syncthreads();
    }
    if (t == 0) g_part[blockIdx.x] = sm[0];
}

__global__ __launch_bounds__(128) void scan2_kernel() {
    __shared__ int sm[2][128];
    int t = threadIdx.x;
    int v = (t < NB_SCAN) ? g_part[t] : 0;
    int pi = 0;
    sm[0][t] = v;
    __syncthreads();
#pragma unroll
    for (int off = 1; off < 128; off <<= 1) {
        int add = (t >= off) ? sm[pi][t - off] : 0;
        sm[pi ^ 1][t] = sm[pi][t] + add;
        pi ^= 1;
        __syncthreads();
    }
    if (t < NB_SCAN) g_partx[t] = sm[pi][t] - v;   // exclusive
}

__global__ __launch_bounds__(SCAN_BLK) void scan3_kernel() {
    __shared__ int sm[2][SCAN_BLK];
    int t = threadIdx.x;
    int i = blockIdx.x * SCAN_BLK + t;
    int v = (i < N_NODES) ? g_cnt[i] : 0;
    int pi = 0;
    sm[0][t] = v;
    __syncthreads();
#pragma unroll
    for (int off = 1; off < SCAN_BLK; off <<= 1) {
        int add = (t >= off) ? sm[pi][t - off] : 0;
        sm[pi ^ 1][t] = sm[pi][t] + add;
        pi ^= 1;
        __syncthreads();
    }
    if (i < N_NODES) {
        int excl = g_partx[blockIdx.x] + sm[pi][t] - v;
        g_off[i] = excl;
        g_cur[i] = excl;
    }
    if (blockIdx.x == 0 && t == 0) g_off[N_NODES] = N_EDGES;
}

__global__ void scatter_kernel(const int* __restrict__ src, const int* __restrict__ dst) {
    int e = blockIdx.x * blockDim.x + threadIdx.x;
    if (e < N_EDGES) {
        int pos = atomicAdd(&g_cur[dst[e]], 1);
        g_es[pos] = make_int2(e, src[e]);
    }
}

// ---------------------------------------------------------------------------
// Fused: TWO warps per dst node (interleaved stride-2 over the CSR range),
// partial (acc, den) combined through smem. Same total traffic as 1-warp
// version; serial chain per warp halved. NO max subtraction.
// lane l: head h=l>>3, k-chunk k0=(l&7)*8.
// Block = 256 threads = 8 warps = 4 dst nodes. Grid = 50000/4 = 12500 exact.
// ---------------------------------------------------------------------------
__global__ __launch_bounds__(256) void fused_kernel(
    const float* __restrict__ ef, float* __restrict__ out) {
    __shared__ float comb[4][32][5];   // [pair][lane][acc0..3, den]

    const int gw = (blockIdx.x * 256 + threadIdx.x) >> 5;   // global warp id
    const int d    = gw >> 1;
    const int half = gw & 1;
    const int lane = threadIdx.x & 31;
    const int pair = (threadIdx.x >> 6);                     // 0..3 within block
    const int h  = lane >> 3;
    const int k0 = (lane & 7) * 8;

    const int beg = __ldg(&g_off[d]);
    const int end = __ldg(&g_off[d + 1]);

    float den = 0.0f;
    float4 acc = make_float4(0.f, 0.f, 0.f, 0.f);

    const int j0 = beg + half;
    if (j0 < end) {
        int2 e0 = __ldg(&g_es[j0]);
        // prefetch one ahead (stride 2)
        int2 e1 = (j0 + 2 < end) ? __ldg(&g_es[j0 + 2]) : e0;

        for (int j = j0; j < end; j += 2) {
            const int eid_c = e0.x;
            const int s_c   = e0.y;
            e0 = e1;
            const int jn = (j + 4 < end) ? j + 4 : j;   // clamped prefetch
            e1 = __ldg(&g_es[jn]);

            const float4 ef0 = *(const float4*)(ef + (size_t)eid_c * EDGE_FEATS + k0);
            const float4 ef1 = *(const float4*)(ef + (size_t)eid_c * EDGE_FEATS + k0 + 4);

            const uint4 qv = *(const uint4*)(g_qh + (size_t)s_c * QCOLS + h * EDGE_FEATS + k0);
            const float2 q0 = __half22float2(*(const __half2*)&qv.x);
            const float2 q1 = __half22float2(*(((const __half2*)&qv.x) + 1));
            const float2 q2 = __half22float2(*(const __half2*)&qv.z);
            const float2 q3 = __half22float2(*(((const __half2*)&qv.z) + 1));

            float p = ef0.x * q0.x + ef0.y * q0.y + ef0.z * q1.x + ef0.w * q1.y
                    + ef1.x * q2.x + ef1.y * q2.y + ef1.z * q3.x + ef1.w * q3.y;
            p += __shfl_xor_sync(0xffffffffu, p, 1);
            p += __shfl_xor_sync(0xffffffffu, p, 2);
            p += __shfl_xor_sync(0xffffffffu, p, 4);

            const float sc = (p > 0.0f) ? p : 0.01f * p;   // leaky relu
            const float w  = __expf(sc);

            const uint2 hvu = *(const uint2*)(g_hh + (size_t)s_c * HF + lane * 4);
            const float2 h01 = __half22float2(*(const __half2*)&hvu.x);
            const float2 h23 = __half22float2(*(const __half2*)&hvu.y);

            den   += w;
            acc.x += w * h01.x;
            acc.y += w * h01.y;
            acc.z += w * h23.x;
            acc.w += w * h23.y;
        }
    }

    // combine the two halves through smem
    if (half == 1) {
        comb[pair][lane][0] = acc.x;
        comb[pair][lane][1] = acc.y;
        comb[pair][lane][2] = acc.z;
        comb[pair][lane][3] = acc.w;
        comb[pair][lane][4] = den;
    }
    __syncthreads();
    if (half == 0) {
        acc.x += comb[pair][lane][0];
        acc.y += comb[pair][lane][1];
        acc.z += comb[pair][lane][2];
        acc.w += comb[pair][lane][3];
        den   += comb[pair][lane][4];

        const float inv = (den > 0.0f) ? __frcp_rn(den) : 0.0f;
        float4 o = make_float4(acc.x * inv, acc.y * inv, acc.z * inv, acc.w * inv);
        *(float4*)(out + (size_t)d * HF + lane * 4) = o;
    }
}

// ---------------------------------------------------------------------------
// True fork/join (no legacy-stream launches inside the forked region).
// ---------------------------------------------------------------------------
extern "C" void kernel_launch(void* const* d_in, const int* in_sizes, int n_in,
                              void* d_out, int out_size) {
    const float* node_feat = (const float*)d_in[0];
    const float* edge_feat = (const float*)d_in[1];
    const int*   src       = (const int*)d_in[2];
    const int*   dst       = (const int*)d_in[3];
    const float* W_node    = (const float*)d_in[4];
    const float* W_edge    = (const float*)d_in[5];
    float* out = (float*)d_out;

    static cudaStream_t sA = nullptr, sB = nullptr;
    static cudaEvent_t evFork = nullptr, evA = nullptr, evB = nullptr;
    if (sA == nullptr) {
        cudaStreamCreateWithFlags(&sA, cudaStreamNonBlocking);
        cudaStreamCreateWithFlags(&sB, cudaStreamNonBlocking);
        cudaEventCreateWithFlags(&evFork, cudaEventDisableTiming);
        cudaEventCreateWithFlags(&evA, cudaEventDisableTiming);
        cudaEventCreateWithFlags(&evB, cudaEventDisableTiming);
    }

    // fork from the capture-origin (default) stream
    cudaEventRecord(evFork, 0);
    cudaStreamWaitEvent(sA, evFork, 0);
    cudaStreamWaitEvent(sB, evFork, 0);

    // branch A: projection GEMM chain on sA
    wcat_kernel<<<IN_FEATS, NCAT, 0, sA>>>(W_node, W_edge);
    {
        dim3 ggrid(3, (N_NODES + GM_BM - 1) / GM_BM);
        gemm_cat_kernel<<<ggrid, 256, 0, sA>>>(node_feat);
    }
    cudaEventRecord(evA, sA);

    // branch B: CSR build on sB
    zero_cnt_kernel<<<(N_NODES + 255) / 256, 256, 0, sB>>>();
    hist_kernel<<<(N_EDGES + 255) / 256, 256, 0, sB>>>(dst);
    scan1_kernel<<<NB_SCAN, SCAN_BLK, 0, sB>>>();
    scan2_kernel<<<1, 128, 0, sB>>>();
    scan3_kernel<<<NB_SCAN, SCAN_BLK, 0, sB>>>();
    scatter_kernel<<<(N_EDGES + 255) / 256, 256, 0, sB>>>(src, dst);
    cudaEventRecord(evB, sB);

    // join on default stream, then consume both branches
    cudaStreamWaitEvent(0, evA, 0);
    cudaStreamWaitEvent(0, evB, 0);
    fused_kernel<<<(N_NODES * 64) / 256, 256>>>(edge_feat, out);
}